// round 7
// baseline (speedup 1.0000x reference)
#include <cuda_runtime.h>
#include <cuda_bf16.h>

// FGRU: B=64, T=1024, D=512, U=512, C=1024
// Persistent kernel: 128 CTAs x 256 threads, 3 grid barriers per timestep.
//
// Data layouts (global scratch, transposed so lanes index consecutive rows):
//   g_hT[u][row]   : hidden state (u in [0,512))
//   g_aT[k][row]   : combined*gate (k in [0,1024))
//   g_zT[u][row]   : pre-LN candidate
// Per-CTA SMEM: Wg cols [8c,8c+8) split by k-range into two layouts:
//   wg_c[col][k]   for k in [0,512)    (x-half, col-major)
//   wg_k[k-512][col] for k in [512,1024) (h-half, k-major)
// Wf cols [4c,4c+4) k-major; activation staging tiles; reduction buffer.

#define NCTA 128
#define NTHR 256

__device__ __align__(16) float g_hT[512 * 64];
__device__ __align__(16) float g_aT[1024 * 64];
__device__ __align__(16) float g_zT[512 * 64];
__device__ unsigned g_cnt;   // zero-initialized, returns to 0 after each barrier
__device__ unsigned g_gen;   // monotonically increasing generation

// SMEM layout (in floats)
#define OFF_WGC 0                         // [8][512] col-major (k in [0,512))
#define OFF_WGK (OFF_WGC + 8 * 512)       // [512][8] k-major  (k-512)
#define OFF_WFK (OFF_WGK + 512 * 8)       // [1024][4] k-major
#define OFF_CA  (OFF_WFK + 1024 * 4)      // [64][132] row-major padded x-tile
#define OFF_CB  (OFF_CA + 64 * 132)       // [128][64] transposed tile
#define OFF_RED (OFF_CB + 128 * 64)       // [64][8] reduction
#define SMEM_FLOATS (OFF_RED + 64 * 8)    // 29,440 floats = 117,760 B

__device__ __forceinline__ void grid_sync(unsigned* genp)
{
    unsigned target = ++(*genp);
    __syncthreads();
    if (threadIdx.x == 0) {
        __threadfence();
        unsigned prev = atomicAdd(&g_cnt, 1u);
        if (prev == NCTA - 1) {
            atomicExch(&g_cnt, 0u);
            __threadfence();
            atomicExch(&g_gen, target);
        } else {
            volatile unsigned* vg = &g_gen;
            while (*vg != target) { }
            __threadfence();
        }
    }
    __syncthreads();
}

__device__ __forceinline__ float sigmoidf_(float v)
{
    return 1.0f / (1.0f + __expf(-v));
}

__global__ void __launch_bounds__(NTHR, 1)
fgru_kernel(const float* __restrict__ x,      // [64][1024][512]
            const float* __restrict__ h0,     // [64][512]
            const float* __restrict__ Wg,     // [1024][1024]
            const float* __restrict__ bg,     // [1024]
            const float* __restrict__ Wf,     // [1024][512]
            const float* __restrict__ bf,     // [512]
            const float* __restrict__ gmm,    // [512]
            const float* __restrict__ bta,    // [512]
            float* __restrict__ y)            // [64][1024][512]
{
    extern __shared__ __align__(16) float sm[];
    float* wg_c  = sm + OFF_WGC;
    float* wg_k  = sm + OFF_WGK;
    float* wf_k  = sm + OFF_WFK;
    float* combA = sm + OFF_CA;
    float* combB = sm + OFF_CB;
    float* red   = sm + OFF_RED;

    const int tid = threadIdx.x;
    const int cta = blockIdx.x;
    const int gc0 = cta * 8;
    const int fc0 = cta * 4;

    // ---- one-time: load weights into SMEM ----
    // Wg cols [gc0, gc0+8): k<512 -> col-major wg_c; k>=512 -> k-major wg_k (k-512)
    for (int e = tid; e < 8192; e += NTHR) {
        int c = e & 7, k = e >> 3;
        float v = Wg[k * 1024 + gc0 + c];
        if (k < 512) wg_c[c * 512 + k] = v;         // [col][k]
        else         wg_k[(k - 512) * 8 + c] = v;   // [k-512][col]
    }
    for (int e = tid; e < 4096; e += NTHR) {
        int c = e & 3, k = e >> 2;
        wf_k[k * 4 + c] = Wf[k * 512 + fc0 + c];
    }

    // ---- one-time: init h_T from h0 (each CTA writes a distinct 256-elem slice) ----
    {
        int idx = cta * NTHR + tid;          // 0..32767
        int u = idx >> 6, row = idx & 63;
        g_hT[idx] = h0[row * 512 + u];       // idx == u*64+row
    }

    // ---- barrier generation base (consistent across CTAs & graph replays) ----
    __shared__ unsigned s_gen;
    if (tid == 0) s_gen = *(volatile unsigned*)&g_gen;
    __syncthreads();
    unsigned gen = s_gen;

    __threadfence();
    grid_sync(&gen);   // h_T + weights visible everywhere

    const float4* x4     = reinterpret_cast<const float4*>(x);
    float4* combA4       = reinterpret_cast<float4*>(combA);
    float4* combB4       = reinterpret_cast<float4*>(combB);
    const float4* wgc4   = reinterpret_cast<const float4*>(wg_c);
    const float4* wgk4   = reinterpret_cast<const float4*>(wg_k);
    const float4* wfk4   = reinterpret_cast<const float4*>(wf_k);
    const float4* hT4    = reinterpret_cast<const float4*>(g_hT);
    const float4* aT4    = reinterpret_cast<const float4*>(g_aT);

    const int row = tid & 63;          // output row (batch index)
    const int cg  = (tid >> 6) & 1;    // x-half col-group (4 cols each)
    const int sx  = tid >> 7;          // x-half k-split (0/1)
    const int s4  = tid >> 6;          // 4-way k-split (0..3)

    for (int step = 0; step < 1024; ++step) {
        // ================= GEMM1, x-half: gate += x_t @ Wg[0:512, cols] ========
        float ax0 = 0.f, ax1 = 0.f, ax2 = 0.f, ax3 = 0.f;
        for (int kc = 0; kc < 4; ++kc) {           // k in [kc*128, kc*128+128)
            // stage x chunk row-major padded: coalesced LDG + conflict-free STS
            #pragma unroll
            for (int i = 0; i < 8; ++i) {
                int f = tid + NTHR * i;            // 0..2047 float4
                int r = f >> 5, kq = f & 31;
                combA4[r * 33 + kq] = x4[(r * 1024 + step) * 128 + kc * 32 + kq];
            }
            __syncthreads();
            const float4* crow = combA4 + row * 33 + sx * 16;
            const float4* p0 = wgc4 + (4 * cg + 0) * 128 + kc * 32 + sx * 16;
            const float4* p1 = p0 + 128;
            const float4* p2 = p0 + 256;
            const float4* p3 = p0 + 384;
            #pragma unroll
            for (int j = 0; j < 16; ++j) {
                float4 c  = crow[j];
                float4 w0 = p0[j], w1 = p1[j], w2 = p2[j], w3 = p3[j];
                ax0 += c.x * w0.x + c.y * w0.y + c.z * w0.z + c.w * w0.w;
                ax1 += c.x * w1.x + c.y * w1.y + c.z * w1.z + c.w * w1.w;
                ax2 += c.x * w2.x + c.y * w2.y + c.z * w2.z + c.w * w2.w;
                ax3 += c.x * w3.x + c.y * w3.y + c.z * w3.z + c.w * w3.w;
            }
            __syncthreads();
        }

        // ================= GEMM1, h-half: gate += h @ Wg[512:1024, cols] =======
        float ah0=0.f,ah1=0.f,ah2=0.f,ah3=0.f,ah4=0.f,ah5=0.f,ah6=0.f,ah7=0.f;
        for (int kc = 0; kc < 4; ++kc) {           // u in [kc*128, kc*128+128)
            #pragma unroll
            for (int i = 0; i < 8; ++i) {
                int f = tid + NTHR * i;
                combB4[f] = hT4[kc * 2048 + f];    // direct copy, already [u][row]
            }
            __syncthreads();
            int kb = s4 * 32;
            #pragma unroll 8
            for (int kk = 0; kk < 32; ++kk) {
                int kl = kb + kk;                  // local u in chunk
                float  c  = combB[kl * 64 + row];
                // wg_k row index = global_k - 512 = kc*128 + kl  (matches layout)
                float4 wa = wgk4[(kc * 128 + kl) * 2 + 0];
                float4 wb = wgk4[(kc * 128 + kl) * 2 + 1];
                ah0 += c * wa.x; ah1 += c * wa.y; ah2 += c * wa.z; ah3 += c * wa.w;
                ah4 += c * wb.x; ah5 += c * wb.y; ah6 += c * wb.z; ah7 += c * wb.w;
            }
            __syncthreads();
        }

        // ================= reduce partials into red[64][8] ======================
        if (sx == 0) {
            red[row * 8 + 4 * cg + 0] = ax0;
            red[row * 8 + 4 * cg + 1] = ax1;
            red[row * 8 + 4 * cg + 2] = ax2;
            red[row * 8 + 4 * cg + 3] = ax3;
        }
        __syncthreads();
        if (sx == 1) {
            red[row * 8 + 4 * cg + 0] += ax0;
            red[row * 8 + 4 * cg + 1] += ax1;
            red[row * 8 + 4 * cg + 2] += ax2;
            red[row * 8 + 4 * cg + 3] += ax3;
        }
        __syncthreads();
        #pragma unroll
        for (int s = 0; s < 4; ++s) {
            if (s4 == s) {
                red[row * 8 + 0] += ah0; red[row * 8 + 1] += ah1;
                red[row * 8 + 2] += ah2; red[row * 8 + 3] += ah3;
                red[row * 8 + 4] += ah4; red[row * 8 + 5] += ah5;
                red[row * 8 + 6] += ah6; red[row * 8 + 7] += ah7;
            }
            __syncthreads();
        }

        // ================= gate = sigmoid(.), a = combined*gate =================
        {
            int cp = tid >> 6;                     // 0..3
            #pragma unroll
            for (int j = 0; j < 2; ++j) {
                int cl = 2 * cp + j;
                int gc = gc0 + cl;
                float pre = red[row * 8 + cl] + bg[gc];
                float gte = sigmoidf_(pre);
                float cv  = (gc < 512) ? x[(row * 1024 + step) * 512 + gc]
                                       : g_hT[(gc - 512) * 64 + row];
                g_aT[gc * 64 + row] = cv * gte;    // coalesced (lanes=rows)
            }
        }
        __threadfence();
        grid_sync(&gen);   // barrier 1: a_T complete

        // ================= GEMM2: z = a @ Wf[:, cols] ===========================
        float za0 = 0.f, za1 = 0.f, za2 = 0.f, za3 = 0.f;
        for (int kc = 0; kc < 8; ++kc) {
            #pragma unroll
            for (int i = 0; i < 8; ++i) {
                int f = tid + NTHR * i;
                combB4[f] = aT4[kc * 2048 + f];
            }
            __syncthreads();
            int kb = s4 * 32;
            #pragma unroll 8
            for (int kk = 0; kk < 32; ++kk) {
                int kl = kb + kk;
                float  c = combB[kl * 64 + row];
                float4 w = wfk4[kc * 128 + kl];
                za0 += c * w.x; za1 += c * w.y; za2 += c * w.z; za3 += c * w.w;
            }
            __syncthreads();
        }
        if (s4 == 0) {
            red[row * 8 + 0] = za0; red[row * 8 + 1] = za1;
            red[row * 8 + 2] = za2; red[row * 8 + 3] = za3;
        }
        __syncthreads();
        #pragma unroll
        for (int s = 1; s < 4; ++s) {
            if (s4 == s) {
                red[row * 8 + 0] += za0; red[row * 8 + 1] += za1;
                red[row * 8 + 2] += za2; red[row * 8 + 3] += za3;
            }
            __syncthreads();
        }
        {
            int col = tid >> 6;                    // 0..3
            float z  = red[row * 8 + col] + bf[fc0 + col];
            float zs = z * sigmoidf_(z);           // silu
            g_zT[(fc0 + col) * 64 + row] = zs;     // coalesced
        }
        __threadfence();
        grid_sync(&gen);   // barrier 2: z_T complete

        // ================= LayerNorm (CTAs 0..63, one row each) =================
        if (cta < 64) {
            int r = cta;
            float v0 = g_zT[tid * 64 + r];
            float v1 = g_zT[(tid + 256) * 64 + r];
            float s  = v0 + v1;
            float ss = v0 * v0 + v1 * v1;
            #pragma unroll
            for (int o = 16; o > 0; o >>= 1) {
                s  += __shfl_xor_sync(0xffffffffu, s,  o);
                ss += __shfl_xor_sync(0xffffffffu, ss, o);
            }
            int warp = tid >> 5, lane = tid & 31;
            if (lane == 0) { red[warp * 2] = s; red[warp * 2 + 1] = ss; }
            __syncthreads();
            float S = 0.f, SS = 0.f;
            #pragma unroll
            for (int w = 0; w < 8; ++w) { S += red[w * 2]; SS += red[w * 2 + 1]; }
            float mu   = S * (1.0f / 512.0f);
            float var  = SS * (1.0f / 512.0f) - mu * mu;
            float rstd = rsqrtf(var + 1e-3f);
            float h0v = (v0 - mu) * rstd * gmm[tid]       + bta[tid];
            float h1v = (v1 - mu) * rstd * gmm[tid + 256] + bta[tid + 256];
            g_hT[tid * 64 + r]         = h0v;
            g_hT[(tid + 256) * 64 + r] = h1v;
            float* yr = y + (r * 1024 + step) * 512;
            yr[tid]       = h0v;     // coalesced
            yr[tid + 256] = h1v;
            __threadfence();
        }
        grid_sync(&gen);   // barrier 3: h_T ready for next step
    }
}

extern "C" void kernel_launch(void* const* d_in, const int* in_sizes, int n_in,
                              void* d_out, int out_size)
{
    const float* x    = (const float*)d_in[0];
    const float* h0   = (const float*)d_in[1];
    const float* Wg   = (const float*)d_in[2];
    const float* bg   = (const float*)d_in[3];
    const float* Wf   = (const float*)d_in[4];
    const float* bf   = (const float*)d_in[5];
    const float* gmm  = (const float*)d_in[6];
    const float* bta  = (const float*)d_in[7];
    float* y = (float*)d_out;

    int smem_bytes = SMEM_FLOATS * (int)sizeof(float);   // 117,760 B
    cudaFuncSetAttribute(fgru_kernel,
                         cudaFuncAttributeMaxDynamicSharedMemorySize, smem_bytes);

    fgru_kernel<<<NCTA, NTHR, smem_bytes>>>(x, h0, Wg, bg, Wf, bf, gmm, bta, y);
}